// round 13
// baseline (speedup 1.0000x reference)
#include <cuda_runtime.h>
#include <cuda_fp8.h>
#include <cstdint>

#define N_PIX   16384
#define N_CODES 16384
#define DIM     256
#define HW      1024

#define PX_CTA  128
#define NTILE   256
#define NCTA    148
#define NTILES_G 8192               // 128 px-tiles x 64 code-tiles
#define GT      1024                // 32 warps: 4M x 8N, warp tile 32x32

#define ASTRB   272                 // A smem row stride bytes (256 + 16)
#define BSTRB   144                 // B smem row stride bytes (128 + 16)
#define A_BYTES      (PX_CTA * ASTRB)     // 34816
#define BSTAGE_BYTES (NTILE * BSTRB)      // 36864
#define NSTAGE  4
#define NS_OFF  (A_BYTES + NSTAGE * BSTAGE_BYTES)   // 182272
#define DYN_BYTES (NS_OFF + 3 * NTILE * 4)          // 185344

#define ZQ_ELEMS (16 * DIM * HW)
#define LOSS_OFF ZQ_ELEMS
#define IDX_OFF  (ZQ_ELEMS + 1)

__device__ uint8_t g_Za[(size_t)N_PIX * DIM];    // e4m3 z, pixel-major
__device__ uint8_t g_Ea[(size_t)N_CODES * DIM];  // e4m3 e, code-major
__device__ float   g_Zte[(size_t)N_PIX * DIM];
__device__ float   g_norm2[N_CODES];
__device__ int     g_seg[NCTA * 2 * PX_CTA * 8]; // per-(CTA,seg,px) top-8 keys
__device__ int     g_segmt[NCTA * 2];

__device__ __forceinline__ uint32_t s2u(const void* p) {
    return (uint32_t)__cvta_generic_to_shared(p);
}
__device__ __forceinline__ void cpasync16(uint32_t dst, const void* src) {
    asm volatile("cp.async.cg.shared.global [%0], [%1], 16;" :: "r"(dst), "l"(src));
}
__device__ __forceinline__ void ldsm4(uint32_t* r, uint32_t addr) {
    asm volatile("ldmatrix.sync.aligned.m8n8.x4.shared.b16 {%0,%1,%2,%3}, [%4];"
                 : "=r"(r[0]), "=r"(r[1]), "=r"(r[2]), "=r"(r[3]) : "r"(addr));
}
__device__ __forceinline__ void mma_fp8(float* c, const uint32_t* a,
                                        const uint32_t* b) {
    asm volatile(
        "mma.sync.aligned.m16n8k32.row.col.f32.e4m3.e4m3.f32 "
        "{%0,%1,%2,%3},{%4,%5,%6,%7},{%8,%9},{%0,%1,%2,%3};"
        : "+f"(c[0]), "+f"(c[1]), "+f"(c[2]), "+f"(c[3])
        : "r"(a[0]), "r"(a[1]), "r"(a[2]), "r"(a[3]), "r"(b[0]), "r"(b[1]));
}
__device__ __forceinline__ uint32_t q8(float v) {
    return (uint32_t)__nv_cvt_float_to_fp8(v, __NV_SATFINITE, __NV_E4M3);
}

// ---------------------------------------------------------------------------
// Merged prep: blocks [0,512) transpose+quantize z; blocks [512,2560) do E.
// ---------------------------------------------------------------------------
__global__ void __launch_bounds__(256)
prep_kernel(const float* __restrict__ z, const float* __restrict__ emb) {
    const int tid = threadIdx.x, lane = tid & 31, wid = tid >> 5;
    if (blockIdx.x < 512) {
        __shared__ float Zs[DIM][33];
        int px0 = blockIdx.x * 32;
        int b = px0 >> 10, hw0 = px0 & (HW - 1);
        for (int i = tid; i < DIM * 32; i += 256) {
            int d = i >> 5, px = i & 31;
            Zs[d][px] = z[((size_t)b * DIM + d) * HW + hw0 + px];
        }
        __syncthreads();
#pragma unroll
        for (int pp = 0; pp < 4; pp++) {
            int px = wid + pp * 8;
            float* rowE = g_Zte + (size_t)(px0 + px) * DIM;
#pragma unroll
            for (int i = 0; i < 8; i++) {
                int d = lane + 32 * i;
                rowE[d] = Zs[d][px];
            }
            uint32_t pk[2] = {0, 0};
#pragma unroll
            for (int t = 0; t < 8; t++) {
                float v = Zs[lane * 8 + t][px];
                pk[t >> 2] |= q8(v) << ((t & 3) * 8);
            }
            *(uint2*)(g_Za + (size_t)(px0 + px) * DIM + lane * 8) =
                make_uint2(pk[0], pk[1]);
        }
    } else {
        int code = (blockIdx.x - 512) * 8 + wid;
        const float* src = emb + (size_t)code * DIM + lane * 8;
        float en = 0.f;
        uint32_t pk[2] = {0, 0};
#pragma unroll
        for (int t = 0; t < 8; t++) {
            float v = src[t];
            en += v * v;
            pk[t >> 2] |= q8(v) << ((t & 3) * 8);
        }
        *(uint2*)(g_Ea + (size_t)code * DIM + lane * 8) = make_uint2(pk[0], pk[1]);
#pragma unroll
        for (int o = 16; o > 0; o >>= 1) en += __shfl_xor_sync(0xffffffffu, en, o);
        if (lane == 0) g_norm2[code] = en;
    }
}

// ---------------------------------------------------------------------------
// B chunk loader (1024 threads): 256 rows x 128 e4m3 bytes; 4 threads/row.
// ---------------------------------------------------------------------------
__device__ __forceinline__ void load_b_chunk(uint32_t dstb, int tg, int kh,
                                             int tid) {
    const int row = tid >> 2, qr = tid & 3;
    const uint8_t* src =
        g_Ea + (size_t)((tg & 63) * NTILE + row) * DIM + kh * 128 + qr * 32;
    uint32_t dst = dstb + row * BSTRB + qr * 32;
    cpasync16(dst, src);
    cpasync16(dst + 16, src + 16);
}

// ---------------------------------------------------------------------------
// GEMM (fp8) over balanced tile ranges; 32 warps, warp tile 32x32; top-8 flush.
// ---------------------------------------------------------------------------
__global__ void __launch_bounds__(GT, 1)
vq_gemm_kernel() {
    extern __shared__ char dsm[];
    char* As = dsm;
    char* Bs = dsm + A_BYTES;
    float* Ns = (float*)(dsm + NS_OFF);

    const int tid = threadIdx.x;
    const int lane = tid & 31;
    const int wid = tid >> 5;
    const int mw = wid >> 3;          // 0..3
    const int nw = wid & 7;           // 0..7
    const int g = lane >> 2;
    const int tig = lane & 3;
    const int c = blockIdx.x;

    const int t0 = (c * NTILES_G) / NCTA;
    const int t1 = ((c + 1) * NTILES_G) / NCTA;

    // fp8 ldsm addressing (byte offsets) — proven in round 9
    const int a_row_l = (lane & 7) + ((lane >> 3) & 1) * 8;
    const int a_col_l = (lane >> 4) * 16;
    const int b_row_l = (lane & 7) + ((lane >> 4) & 1) * 8;
    const int b_col_l = ((lane >> 3) & 1) * 16;

    int seg = 0;
    int t = t0;
    while (t < t1) {
        const int mt = t >> 6;                    // px-tile
        const int tend = min(t1, (mt + 1) << 6);
        const int nchunks = (tend - t) * 2;       // chunk = 128 dims
        const int p0 = mt * PX_CTA;

        // ---- segment prologue ----
        {
            int r = tid >> 3, q = tid & 7;   // 128 rows, 8 threads/row, 32B each
            const uint8_t* src = g_Za + (size_t)(p0 + r) * DIM + q * 32;
            uint32_t dst = s2u(As + r * ASTRB + q * 32);
            cpasync16(dst, src);
            cpasync16(dst + 16, src + 16);
        }
        load_b_chunk(s2u(Bs), t, 0, tid);
        if (tid < 64)
            cpasync16(s2u(Ns + (t % 3) * NTILE + tid * 4),
                      g_norm2 + (size_t)(t & 63) * NTILE + tid * 4);
        asm volatile("cp.async.commit_group;" ::: "memory");
        load_b_chunk(s2u(Bs + BSTAGE_BYTES), t, 1, tid);
        asm volatile("cp.async.commit_group;" ::: "memory");
        load_b_chunk(s2u(Bs + 2 * BSTAGE_BYTES), t + 1, 0, tid);
        if (tid < 64 && t + 1 < tend)
            cpasync16(s2u(Ns + ((t + 1) % 3) * NTILE + tid * 4),
                      g_norm2 + (size_t)((t + 1) & 63) * NTILE + tid * 4);
        asm volatile("cp.async.commit_group;" ::: "memory");

        float acc[2][4][4];
#pragma unroll
        for (int mq = 0; mq < 2; mq++)
#pragma unroll
            for (int nt = 0; nt < 4; nt++)
#pragma unroll
                for (int r = 0; r < 4; r++) acc[mq][nt][r] = 0.f;

        int v1[4], v2[4];
#pragma unroll
        for (int s = 0; s < 4; s++) { v1[s] = INT_MIN; v2[s] = INT_MIN; }

        for (int cc = 0; cc < nchunks; cc++) {
            asm volatile("cp.async.wait_group 2;" ::: "memory");
            __syncthreads();

            if (cc + 3 < nchunks) {
                const int nx = cc + 3;
                const int tt = t + (nx >> 1), kh = nx & 1;
                load_b_chunk(s2u(Bs + (nx & 3) * BSTAGE_BYTES), tt, kh, tid);
                if (kh == 0 && tid < 64)
                    cpasync16(s2u(Ns + (tt % 3) * NTILE + tid * 4),
                              g_norm2 + (size_t)(tt & 63) * NTILE + tid * 4);
            }
            asm volatile("cp.async.commit_group;" ::: "memory");

            // compute chunk cc: 4 k32-steps; A k-byte offset = (cc&1)*128
            const char* sb = Bs + (cc & 3) * BSTAGE_BYTES;
            const int kb0 = (cc & 1) * 128;
#pragma unroll
            for (int s = 0; s < 4; s++) {
                uint32_t a[2][4];
#pragma unroll
                for (int mq = 0; mq < 2; mq++) {
                    uint32_t addr = s2u(As + (mw * 32 + mq * 16 + a_row_l) *
                                        ASTRB + kb0 + s * 32 + a_col_l);
                    ldsm4(a[mq], addr);
                }
                uint32_t b[4][2];
#pragma unroll
                for (int np = 0; np < 2; np++) {
                    uint32_t r[4];
                    uint32_t addr = s2u(sb + (nw * 32 + np * 16 + b_row_l) *
                                        BSTRB + s * 32 + b_col_l);
                    ldsm4(r, addr);
                    b[2 * np][0] = r[0]; b[2 * np][1] = r[1];
                    b[2 * np + 1][0] = r[2]; b[2 * np + 1][1] = r[3];
                }
#pragma unroll
                for (int mq = 0; mq < 2; mq++)
#pragma unroll
                    for (int nt = 0; nt < 4; nt++)
                        mma_fp8(acc[mq][nt], a[mq], b[nt]);
            }

            // fold tile every 2 chunks (branch-free int-packed top-2 per slot)
            if (cc & 1) {
                const int ti = t + (cc >> 1);
                const float2* nsp = (const float2*)(Ns + (ti % 3) * NTILE);
                const int cb = (ti & 63) * NTILE;
#pragma unroll
                for (int nt = 0; nt < 4; nt++) {
                    float2 nn = nsp[nw * 16 + nt * 4 + tig];
                    const int c0 = cb + nw * 32 + nt * 8 + 2 * tig;
#pragma unroll
                    for (int mq = 0; mq < 2; mq++) {
#pragma unroll
                        for (int r = 0; r < 4; r++) {
                            float nrm = (r & 1) ? nn.y : nn.x;
                            float sv = fmaf(nrm, -0.5f, acc[mq][nt][r]);
                            int key = __float2int_rn(sv * 128.0f) * 16384 +
                                      (c0 + (r & 1));
                            const int sl = mq * 2 + (r >> 1);
                            int nv1 = max(v1[sl], key);
                            v2[sl] = max(v2[sl], min(v1[sl], key));
                            v1[sl] = nv1;
                            acc[mq][nt][r] = 0.f;
                        }
                    }
                }
            }
        }

        // ---- segment epilogue: drain, block top-8, flush ----
        asm volatile("cp.async.wait_group 0;" ::: "memory");
        __syncthreads();
        int2* red = (int2*)dsm;   // reuse A region: [128 px][32 contributors]
#pragma unroll
        for (int s = 0; s < 4; s++) {
            int pxl = mw * 32 + (s >> 1) * 16 + (s & 1) * 8 + g;
            red[pxl * 32 + nw * 4 + tig] = make_int2(v1[s], v2[s]);
        }
        __syncthreads();
        if (tid < PX_CTA) {
            int b8[8];
#pragma unroll
            for (int i = 0; i < 8; i++) b8[i] = INT_MIN;
#pragma unroll 4
            for (int q = 0; q < 32; q++) {
                int2 e = red[tid * 32 + q];
#pragma unroll
                for (int h = 0; h < 2; h++) {
                    int k = h ? e.y : e.x;
#pragma unroll
                    for (int i = 0; i < 8; i++) {
                        int hi = max(b8[i], k), lo = min(b8[i], k);
                        b8[i] = hi; k = lo;
                    }
                }
            }
            int* dst = g_seg + ((size_t)(c * 2 + seg) * PX_CTA + tid) * 8;
#pragma unroll
            for (int i = 0; i < 8; i++) dst[i] = b8[i];
        }
        if (tid == 0) g_segmt[c * 2 + seg] = mt;
        __syncthreads();   // red read before next segment's A overwrite

        seg++;
        t = tend;
    }
    if (seg < 2 && tid == 0) g_segmt[c * 2 + 1] = -1;
}

// ---------------------------------------------------------------------------
// Merge segments + top-8 exact fp32 rescore + gather. Grid = 128.
// ---------------------------------------------------------------------------
__global__ void __launch_bounds__(256)
merge_kernel(const float* __restrict__ emb, float* __restrict__ out) {
    __shared__ int s_mt[NCTA * 2];
    __shared__ int s_cand[PX_CTA][8];
    __shared__ int s_sel[PX_CTA];
    const int tid = threadIdx.x, lane = tid & 31, wid = tid >> 5;
    const int mt = blockIdx.x;
    const int p0 = mt * PX_CTA;

    for (int j = tid; j < NCTA * 2; j += 256) s_mt[j] = g_segmt[j];
    __syncthreads();

    if (tid < PX_CTA) {
        int b8[8];
#pragma unroll
        for (int i = 0; i < 8; i++) b8[i] = INT_MIN;
        for (int j = 0; j < NCTA * 2; j++) {
            if (s_mt[j] == mt) {
                const int* src = g_seg + ((size_t)j * PX_CTA + tid) * 8;
#pragma unroll
                for (int q = 0; q < 8; q++) {
                    int k = src[q];
#pragma unroll
                    for (int i = 0; i < 8; i++) {
                        int hi = max(b8[i], k), lo = min(b8[i], k);
                        b8[i] = hi; k = lo;
                    }
                }
            }
        }
#pragma unroll
        for (int i = 0; i < 8; i++) s_cand[tid][i] = b8[i] & 16383;
    }
    __syncthreads();

    // exact fp32 rescore of 8 candidates; warp handles 16 pixels
#pragma unroll 1
    for (int j = 0; j < 16; j++) {
        const int pxl = wid * 16 + j;
        const int px = p0 + pxl;
        const float4* zp = (const float4*)(g_Zte + (size_t)px * DIM);
        float4 zv0 = zp[lane], zv1 = zp[lane + 32];
        float sc[8];
#pragma unroll
        for (int cq = 0; cq < 8; cq += 4) {
            const float4* e0 = (const float4*)(emb + (size_t)s_cand[pxl][cq] * DIM);
            const float4* e1 = (const float4*)(emb + (size_t)s_cand[pxl][cq + 1] * DIM);
            const float4* e2 = (const float4*)(emb + (size_t)s_cand[pxl][cq + 2] * DIM);
            const float4* e3 = (const float4*)(emb + (size_t)s_cand[pxl][cq + 3] * DIM);
            float d0 = 0.f, d1 = 0.f, d2 = 0.f, d3 = 0.f;
#pragma unroll
            for (int q = 0; q < 2; q++) {
                float4 zv = q ? zv1 : zv0;
                float4 a = e0[lane + 32 * q];
                float4 b = e1[lane + 32 * q];
                float4 cx = e2[lane + 32 * q];
                float4 d = e3[lane + 32 * q];
                d0 += zv.x * a.x + zv.y * a.y + zv.z * a.z + zv.w * a.w;
                d1 += zv.x * b.x + zv.y * b.y + zv.z * b.z + zv.w * b.w;
                d2 += zv.x * cx.x + zv.y * cx.y + zv.z * cx.z + zv.w * cx.w;
                d3 += zv.x * d.x + zv.y * d.y + zv.z * d.z + zv.w * d.w;
            }
#pragma unroll
            for (int o = 16; o > 0; o >>= 1) {
                d0 += __shfl_xor_sync(0xffffffffu, d0, o);
                d1 += __shfl_xor_sync(0xffffffffu, d1, o);
                d2 += __shfl_xor_sync(0xffffffffu, d2, o);
                d3 += __shfl_xor_sync(0xffffffffu, d3, o);
            }
            sc[cq] = d0; sc[cq + 1] = d1; sc[cq + 2] = d2; sc[cq + 3] = d3;
        }
        if (lane == 0) {
            int best = -1;
            float bs = -3.4e38f;
#pragma unroll
            for (int i = 0; i < 8; i++) {
                int idx = s_cand[pxl][i];
                float s = sc[i] - 0.5f * g_norm2[idx];
                if (s > bs || (s == bs && idx < best)) { bs = s; best = idx; }
            }
            s_sel[pxl] = best;
            out[IDX_OFF + px] = (float)best;
        }
    }
    __syncthreads();

    // gather z_q in NCHW
    const int b = p0 >> 10;
    const int hw0 = p0 & (HW - 1);
    for (int i = tid; i < DIM * PX_CTA; i += 256) {
        int d = i >> 7, pxl = i & 127;
        out[((size_t)b * DIM + d) * HW + hw0 + pxl] =
            emb[(size_t)s_sel[pxl] * DIM + d];
    }
    if (blockIdx.x == 0 && tid == 0) out[LOSS_OFF] = 0.f;
}

// ---------------------------------------------------------------------------
extern "C" void kernel_launch(void* const* d_in, const int* in_sizes, int n_in,
                              void* d_out, int out_size) {
    const float* z = (const float*)d_in[0];
    const float* emb = (const float*)d_in[1];
    float* out = (float*)d_out;
    (void)in_sizes; (void)n_in; (void)out_size;

    static bool attr_set = false;
    if (!attr_set) {
        cudaFuncSetAttribute(vq_gemm_kernel,
                             cudaFuncAttributeMaxDynamicSharedMemorySize,
                             DYN_BYTES);
        attr_set = true;
    }

    prep_kernel<<<2560, 256>>>(z, emb);
    vq_gemm_kernel<<<NCTA, GT, DYN_BYTES>>>();
    merge_kernel<<<N_PIX / PX_CTA, 256>>>(emb, out);
}

// round 14
// speedup vs baseline: 1.2203x; 1.2203x over previous
#include <cuda_runtime.h>
#include <cuda_fp16.h>
#include <cstdint>

#define N_PIX   16384
#define N_CODES 16384
#define DIM     256
#define HW      1024

#define PX_CTA  256
#define NTILE   128
#define KC      64
#define NCTA    148
#define NTILES_G 8192               // 64 px-tiles x 128 code-tiles
#define GT      1024                // 32 warps: 8M x 4N, warp tile 32x32

#define ASTR    264                 // A smem row stride (f16)
#define BSTR    72                  // B smem row stride (f16)
#define A_BYTES      (PX_CTA * ASTR * 2)   // 135168
#define BSTAGE_BYTES (NTILE * BSTR * 2)    // 18432
#define NSTAGE  4
#define NS_OFF  (A_BYTES + NSTAGE * BSTAGE_BYTES)
#define DYN_BYTES (NS_OFF + 2 * NTILE * 4) // 210944

#define ZQ_ELEMS (16 * DIM * HW)
#define LOSS_OFF ZQ_ELEMS
#define IDX_OFF  (ZQ_ELEMS + 1)

__device__ __half g_Zh[(size_t)N_PIX * DIM];
__device__ __half g_Eh[(size_t)N_CODES * DIM];
__device__ float  g_Zte[(size_t)N_PIX * DIM];
__device__ float  g_norm2[N_CODES];
__device__ int2   g_seg[NCTA * 2 * PX_CTA];
__device__ int    g_segmt[NCTA * 2];

__device__ __forceinline__ uint32_t s2u(const void* p) {
    return (uint32_t)__cvta_generic_to_shared(p);
}
__device__ __forceinline__ void cpasync16(uint32_t dst, const void* src) {
    asm volatile("cp.async.cg.shared.global [%0], [%1], 16;" :: "r"(dst), "l"(src));
}
__device__ __forceinline__ void ldsm4(uint32_t* r, uint32_t addr) {
    asm volatile("ldmatrix.sync.aligned.m8n8.x4.shared.b16 {%0,%1,%2,%3}, [%4];"
                 : "=r"(r[0]), "=r"(r[1]), "=r"(r[2]), "=r"(r[3]) : "r"(addr));
}
__device__ __forceinline__ void mma_f16(float* c, const uint32_t* a,
                                        const uint32_t* b) {
    asm volatile(
        "mma.sync.aligned.m16n8k16.row.col.f32.f16.f16.f32 "
        "{%0,%1,%2,%3},{%4,%5,%6,%7},{%8,%9},{%0,%1,%2,%3};"
        : "+f"(c[0]), "+f"(c[1]), "+f"(c[2]), "+f"(c[3])
        : "r"(a[0]), "r"(a[1]), "r"(a[2]), "r"(a[3]), "r"(b[0]), "r"(b[1]));
}

// ---------------------------------------------------------------------------
// Merged prep: blocks [0,512) transpose+convert z; blocks [512,2560) do E.
// ---------------------------------------------------------------------------
__global__ void __launch_bounds__(256)
prep_kernel(const float* __restrict__ z, const float* __restrict__ emb) {
    const int tid = threadIdx.x, lane = tid & 31, wid = tid >> 5;
    if (blockIdx.x < 512) {
        __shared__ float Zs[DIM][33];
        int px0 = blockIdx.x * 32;
        int b = px0 >> 10, hw0 = px0 & (HW - 1);
        for (int i = tid; i < DIM * 32; i += 256) {
            int d = i >> 5, px = i & 31;
            Zs[d][px] = z[((size_t)b * DIM + d) * HW + hw0 + px];
        }
        __syncthreads();
#pragma unroll
        for (int pp = 0; pp < 4; pp++) {
            int px = wid + pp * 8;
            __half* rowH = g_Zh + (size_t)(px0 + px) * DIM;
            float* rowE = g_Zte + (size_t)(px0 + px) * DIM;
#pragma unroll
            for (int i = 0; i < 8; i++) {
                int d = lane + 32 * i;
                float v = Zs[d][px];
                rowH[d] = __float2half_rn(v);
                rowE[d] = v;
            }
        }
    } else {
        int code = (blockIdx.x - 512) * 8 + wid;
        const float* src = emb + (size_t)code * DIM + lane * 8;
        __half* row = g_Eh + (size_t)code * DIM;
        float en = 0.f;
#pragma unroll
        for (int t = 0; t < 8; t++) {
            float v = src[t];
            en += v * v;
            row[lane * 8 + t] = __float2half_rn(v);
        }
#pragma unroll
        for (int o = 16; o > 0; o >>= 1) en += __shfl_xor_sync(0xffffffffu, en, o);
        if (lane == 0) g_norm2[code] = en;
    }
}

// ---------------------------------------------------------------------------
// B chunk loader (1024 threads): 128 rows x 64 f16 (128B); 8 threads/row,
// one 16B cp.async per thread.
// ---------------------------------------------------------------------------
__device__ __forceinline__ void load_b_chunk(uint32_t dstb, int tg, int kn,
                                             int tid) {
    const int row = tid >> 3, qr = tid & 7;
    const __half* src = g_Eh +
        (size_t)((tg & 127) * NTILE + row) * DIM + kn * KC + qr * 8;
    cpasync16(dstb + row * (BSTR * 2) + qr * 16, src);
}

// ---------------------------------------------------------------------------
// GEMM over balanced contiguous tile ranges; 32 warps, warp tile 32x32,
// CTA tile 256px x 128 codes (halved B traffic / cp.async issues).
// ---------------------------------------------------------------------------
__global__ void __launch_bounds__(GT, 1)
vq_gemm_kernel() {
    extern __shared__ char dsm[];
    __half* As = (__half*)dsm;
    char* Bs = dsm + A_BYTES;
    float* Ns = (float*)(dsm + NS_OFF);

    const int tid = threadIdx.x;
    const int lane = tid & 31;
    const int wid = tid >> 5;
    const int mw = wid >> 2;          // 0..7  (M slice, 32 rows each)
    const int nw = wid & 3;           // 0..3  (N slice, 32 codes each)
    const int g = lane >> 2;
    const int tig = lane & 3;
    const int c = blockIdx.x;

    const int t0 = (c * NTILES_G) / NCTA;
    const int t1 = ((c + 1) * NTILES_G) / NCTA;

    const int a_row_l = (lane & 7) + ((lane >> 3) & 1) * 8;
    const int a_col_l = (lane >> 4) * 8;
    const int b_row_l = ((lane >> 4) & 1) * 8 + (lane & 7);
    const int b_col_l = ((lane >> 3) & 1) * 8;

    int seg = 0;
    int t = t0;
    while (t < t1) {
        const int mt = t >> 7;                    // px-tile (128 code-tiles each)
        const int tend = min(t1, (mt + 1) << 7);
        const int nchunks = (tend - t) * 4;
        const int p0 = mt * PX_CTA;

        // ---- segment prologue: A panel + chunk0(+norms) ; chunk1 ; chunk2 ----
        {
            int r = tid >> 2, q = tid & 3;   // 256 rows, 4 threads/row, 128B
            const __half* src = g_Zh + (size_t)(p0 + r) * DIM + q * 64;
            uint32_t dst = s2u(As + r * ASTR + q * 64);
#pragma unroll
            for (int j = 0; j < 8; j++) cpasync16(dst + j * 16, src + j * 8);
        }
        load_b_chunk(s2u(Bs), t, 0, tid);
        if (tid < 32)
            cpasync16(s2u(Ns + (t & 1) * NTILE + tid * 4),
                      g_norm2 + (size_t)(t & 127) * NTILE + tid * 4);
        asm volatile("cp.async.commit_group;" ::: "memory");
        load_b_chunk(s2u(Bs + BSTAGE_BYTES), t, 1, tid);
        asm volatile("cp.async.commit_group;" ::: "memory");
        load_b_chunk(s2u(Bs + 2 * BSTAGE_BYTES), t, 2, tid);
        asm volatile("cp.async.commit_group;" ::: "memory");

        float acc[2][4][4];
#pragma unroll
        for (int mq = 0; mq < 2; mq++)
#pragma unroll
            for (int nt = 0; nt < 4; nt++)
#pragma unroll
                for (int r = 0; r < 4; r++) acc[mq][nt][r] = 0.f;

        int v1[4], v2[4];
#pragma unroll
        for (int s = 0; s < 4; s++) { v1[s] = INT_MIN; v2[s] = INT_MIN; }

        for (int cc = 0; cc < nchunks; cc++) {
            asm volatile("cp.async.wait_group 2;" ::: "memory");
            __syncthreads();

            if (cc + 3 < nchunks) {
                const int nx = cc + 3;
                const int tt = t + (nx >> 2), kn = nx & 3;
                load_b_chunk(s2u(Bs + (nx & 3) * BSTAGE_BYTES), tt, kn, tid);
                if (kn == 0 && tid < 32)
                    cpasync16(s2u(Ns + (tt & 1) * NTILE + tid * 4),
                              g_norm2 + (size_t)(tt & 127) * NTILE + tid * 4);
            }
            asm volatile("cp.async.commit_group;" ::: "memory");

            const char* sb = Bs + (cc & 3) * BSTAGE_BYTES;
            const int kb0 = (cc & 3) * KC;
#pragma unroll
            for (int s = 0; s < 4; s++) {
                uint32_t a[2][4];
#pragma unroll
                for (int mq = 0; mq < 2; mq++) {
                    uint32_t addr = s2u(As + (mw * 32 + mq * 16 + a_row_l) *
                                        ASTR + kb0 + s * 16 + a_col_l);
                    ldsm4(a[mq], addr);
                }
                uint32_t b[4][2];
#pragma unroll
                for (int np = 0; np < 2; np++) {
                    uint32_t r[4];
                    uint32_t addr = s2u(sb + (nw * 32 + np * 16 + b_row_l) *
                                        (BSTR * 2) + (s * 16 + b_col_l) * 2);
                    ldsm4(r, addr);
                    b[2 * np][0] = r[0]; b[2 * np][1] = r[1];
                    b[2 * np + 1][0] = r[2]; b[2 * np + 1][1] = r[3];
                }
#pragma unroll
                for (int mq = 0; mq < 2; mq++)
#pragma unroll
                    for (int nt = 0; nt < 4; nt++)
                        mma_f16(acc[mq][nt], a[mq], b[nt]);
            }

            // fold code-tile every 4 chunks (branch-free int-packed top-2)
            if ((cc & 3) == 3) {
                const int ti = t + (cc >> 2);
                const float2* nsp = (const float2*)(Ns + (ti & 1) * NTILE);
                const int cb = (ti & 127) * NTILE;
#pragma unroll
                for (int nt = 0; nt < 4; nt++) {
                    float2 nn = nsp[nw * 16 + nt * 4 + tig];
                    const int c0 = cb + nw * 32 + nt * 8 + 2 * tig;
#pragma unroll
                    for (int mq = 0; mq < 2; mq++) {
#pragma unroll
                        for (int r = 0; r < 4; r++) {
                            float nrm = (r & 1) ? nn.y : nn.x;
                            float sv = fmaf(nrm, -0.5f, acc[mq][nt][r]);
                            int key = __float2int_rn(sv * 128.0f) * 16384 +
                                      (c0 + (r & 1));
                            const int sl = mq * 2 + (r >> 1);
                            int nv1 = max(v1[sl], key);
                            v2[sl] = max(v2[sl], min(v1[sl], key));
                            v1[sl] = nv1;
                            acc[mq][nt][r] = 0.f;
                        }
                    }
                }
            }
        }

        // ---- segment epilogue: drain, block-reduce top-2, flush ----
        asm volatile("cp.async.wait_group 0;" ::: "memory");
        __syncthreads();
        int2* red = (int2*)dsm;   // reuse A region: [256 px][16 contributors]
#pragma unroll
        for (int s = 0; s < 4; s++) {
            int pxl = mw * 32 + (s >> 1) * 16 + (s & 1) * 8 + g;
            red[pxl * 16 + nw * 4 + tig] = make_int2(v1[s], v2[s]);
        }
        __syncthreads();
        if (tid < PX_CTA) {
            int bv1 = INT_MIN, bv2 = INT_MIN;
#pragma unroll
            for (int q = 0; q < 16; q++) {
                int2 e = red[tid * 16 + q];
                int nv1 = max(bv1, e.x);
                bv2 = max(bv2, min(bv1, e.x));
                bv1 = nv1;
                nv1 = max(bv1, e.y);
                bv2 = max(bv2, min(bv1, e.y));
                bv1 = nv1;
            }
            g_seg[(c * 2 + seg) * PX_CTA + tid] = make_int2(bv1, bv2);
        }
        if (tid == 0) g_segmt[c * 2 + seg] = mt;
        __syncthreads();   // red read before next segment's A overwrite

        seg++;
        t = tend;
    }
    if (seg < 2 && tid == 0) g_segmt[c * 2 + 1] = -1;
}

// ---------------------------------------------------------------------------
// Merge segments per px-tile + exact fp32 rescore + gather. Grid = 64.
// ---------------------------------------------------------------------------
__global__ void __launch_bounds__(256)
merge_kernel(const float* __restrict__ emb, float* __restrict__ out) {
    __shared__ int s_mt[NCTA * 2];
    __shared__ int2 s_cand[PX_CTA];
    __shared__ int s_sel[PX_CTA];
    const int tid = threadIdx.x, lane = tid & 31, wid = tid >> 5;
    const int mt = blockIdx.x;
    const int p0 = mt * PX_CTA;

    for (int j = tid; j < NCTA * 2; j += 256) s_mt[j] = g_segmt[j];
    __syncthreads();

    if (tid < PX_CTA) {
        int bv1 = INT_MIN, bv2 = INT_MIN;
        for (int j = 0; j < NCTA * 2; j++) {
            if (s_mt[j] == mt) {
                int2 e = g_seg[j * PX_CTA + tid];
                int nv1 = max(bv1, e.x);
                bv2 = max(bv2, min(bv1, e.x));
                bv1 = nv1;
                nv1 = max(bv1, e.y);
                bv2 = max(bv2, min(bv1, e.y));
                bv1 = nv1;
            }
        }
        s_cand[tid] = make_int2(bv1 & 16383, bv2 & 16383);
    }
    __syncthreads();

    // exact fp32 rescore of the 2 candidates; warp handles 32 pixels
#pragma unroll 1
    for (int j = 0; j < 32; j++) {
        const int pxl = wid * 32 + j;
        const int px = p0 + pxl;
        const int2 cand = s_cand[pxl];
        const float4* zp = (const float4*)(g_Zte + (size_t)px * DIM);
        const float4* e1 = (const float4*)(emb + (size_t)cand.x * DIM);
        const float4* e2 = (const float4*)(emb + (size_t)cand.y * DIM);
        float d1 = 0.f, d2 = 0.f;
#pragma unroll
        for (int q = 0; q < 2; q++) {
            float4 zv = zp[lane + 32 * q];
            float4 a = e1[lane + 32 * q];
            float4 b = e2[lane + 32 * q];
            d1 += zv.x * a.x + zv.y * a.y + zv.z * a.z + zv.w * a.w;
            d2 += zv.x * b.x + zv.y * b.y + zv.z * b.z + zv.w * b.w;
        }
#pragma unroll
        for (int o = 16; o > 0; o >>= 1) {
            d1 += __shfl_xor_sync(0xffffffffu, d1, o);
            d2 += __shfl_xor_sync(0xffffffffu, d2, o);
        }
        if (lane == 0) {
            float s1 = d1 - 0.5f * g_norm2[cand.x];
            float s2 = d2 - 0.5f * g_norm2[cand.y];
            int best;
            if (s1 > s2) best = cand.x;
            else if (s2 > s1) best = cand.y;
            else best = min(cand.x, cand.y);
            s_sel[pxl] = best;
            out[IDX_OFF + px] = (float)best;
        }
    }
    __syncthreads();

    // gather z_q in NCHW
    const int b = p0 >> 10;
    const int hw0 = p0 & (HW - 1);
    for (int i = tid; i < DIM * PX_CTA; i += 256) {
        int d = i >> 8, pxl = i & 255;
        out[((size_t)b * DIM + d) * HW + hw0 + pxl] =
            emb[(size_t)s_sel[pxl] * DIM + d];
    }
    if (blockIdx.x == 0 && tid == 0) out[LOSS_OFF] = 0.f;
}

// ---------------------------------------------------------------------------
extern "C" void kernel_launch(void* const* d_in, const int* in_sizes, int n_in,
                              void* d_out, int out_size) {
    const float* z = (const float*)d_in[0];
    const float* emb = (const float*)d_in[1];
    float* out = (float*)d_out;
    (void)in_sizes; (void)n_in; (void)out_size;

    static bool attr_set = false;
    if (!attr_set) {
        cudaFuncSetAttribute(vq_gemm_kernel,
                             cudaFuncAttributeMaxDynamicSharedMemorySize,
                             DYN_BYTES);
        attr_set = true;
    }

    prep_kernel<<<2560, 256>>>(z, emb);
    vq_gemm_kernel<<<NCTA, GT, DYN_BYTES>>>();
    merge_kernel<<<N_PIX / PX_CTA, 256>>>(emb, out);
}

// round 15
// speedup vs baseline: 1.2267x; 1.0052x over previous
#include <cuda_runtime.h>
#include <cuda_fp16.h>
#include <cstdint>

#define N_PIX   16384
#define N_CODES 16384
#define DIM     256
#define HW      1024

#define PX_CTA  128
#define NTILE   256
#define KC      64
#define NCTA    148
#define NTILES_G 8192               // 128 px-tiles x 64 code-tiles
#define GT      1024                // 32 warps: 4M x 8N, warp tile 32x32

#define ASTR    264                 // A smem row stride (f16)
#define BSTR    72                  // B smem row stride (f16)
#define A_BYTES      (PX_CTA * ASTR * 2)   // 67584
#define BSTAGE_BYTES (NTILE * BSTR * 2)    // 36864
#define NSTAGE  4
#define NS_OFF  (A_BYTES + NSTAGE * BSTAGE_BYTES)
#define DYN_BYTES (NS_OFF + 2 * NTILE * 4) // 217088

#define ZQ_ELEMS (16 * DIM * HW)
#define LOSS_OFF ZQ_ELEMS
#define IDX_OFF  (ZQ_ELEMS + 1)

__device__ __half g_Zh[(size_t)N_PIX * DIM];
__device__ __half g_Eh[(size_t)N_CODES * DIM];
__device__ float  g_Zte[(size_t)N_PIX * DIM];
__device__ float  g_norm2[N_CODES];
__device__ int2   g_seg[NCTA * 2 * PX_CTA];
__device__ int    g_segmt[NCTA * 2];

// self-resetting grid barrier state (wrap + phase flip; replay-safe)
__device__ volatile int g_phase;
__device__ unsigned int g_barcnt;

__device__ __forceinline__ void grid_bar() {
    __syncthreads();
    if (threadIdx.x == 0) {
        __threadfence();
        int ph = g_phase;
        if (atomicInc(&g_barcnt, NCTA - 1) == NCTA - 1) {
            g_phase = ph ^ 1;            // last arrival releases
        } else {
            while (g_phase == ph) { }    // volatile spin
        }
        __threadfence();
    }
    __syncthreads();
}

__device__ __forceinline__ uint32_t s2u(const void* p) {
    return (uint32_t)__cvta_generic_to_shared(p);
}
__device__ __forceinline__ void cpasync16(uint32_t dst, const void* src) {
    asm volatile("cp.async.cg.shared.global [%0], [%1], 16;" :: "r"(dst), "l"(src));
}
__device__ __forceinline__ void ldsm4(uint32_t* r, uint32_t addr) {
    asm volatile("ldmatrix.sync.aligned.m8n8.x4.shared.b16 {%0,%1,%2,%3}, [%4];"
                 : "=r"(r[0]), "=r"(r[1]), "=r"(r[2]), "=r"(r[3]) : "r"(addr));
}
__device__ __forceinline__ void mma_f16(float* c, const uint32_t* a,
                                        const uint32_t* b) {
    asm volatile(
        "mma.sync.aligned.m16n8k16.row.col.f32.f16.f16.f32 "
        "{%0,%1,%2,%3},{%4,%5,%6,%7},{%8,%9},{%0,%1,%2,%3};"
        : "+f"(c[0]), "+f"(c[1]), "+f"(c[2]), "+f"(c[3])
        : "r"(a[0]), "r"(a[1]), "r"(a[2]), "r"(a[3]), "r"(b[0]), "r"(b[1]));
}

// ---------------------------------------------------------------------------
// B chunk loader (1024 threads): 256 rows x 64 f16 (128B); 4 threads/row.
// ---------------------------------------------------------------------------
__device__ __forceinline__ void load_b_chunk(uint32_t dstb, int tg, int kn,
                                             int tid) {
    const int row = tid >> 2, qr = tid & 3;
    const __half* src = g_Eh +
        (size_t)((tg & 63) * NTILE + row) * DIM + kn * KC + qr * 16;
    uint32_t dst = dstb + row * (BSTR * 2) + qr * 32;
    cpasync16(dst, src);
    cpasync16(dst + 16, src + 8);
}

// ---------------------------------------------------------------------------
// Fused persistent kernel: prep -> grid_bar -> GEMM -> grid_bar -> merge.
// ---------------------------------------------------------------------------
__global__ void __launch_bounds__(GT, 1)
vq_fused_kernel(const float* __restrict__ z, const float* __restrict__ emb,
                float* __restrict__ out) {
    extern __shared__ char dsm[];
    const int tid = threadIdx.x;
    const int lane = tid & 31;
    const int wid = tid >> 5;
    const int c = blockIdx.x;

    // ================= phase 1: prep =================
    {
        // Z: 512 blocks of 32 pixels, strided over CTAs
        float (*Zs)[33] = (float(*)[33])dsm;   // 256 x 33 floats
        for (int u = c; u < 512; u += NCTA) {
            int px0 = u * 32;
            int b = px0 >> 10, hw0 = px0 & (HW - 1);
            __syncthreads();
            for (int i = tid; i < DIM * 32; i += GT) {
                int d = i >> 5, px = i & 31;
                Zs[d][px] = z[((size_t)b * DIM + d) * HW + hw0 + px];
            }
            __syncthreads();
            {
                int px = wid;   // 32 warps, one pixel each
                __half* rowH = g_Zh + (size_t)(px0 + px) * DIM;
                float* rowE = g_Zte + (size_t)(px0 + px) * DIM;
#pragma unroll
                for (int i = 0; i < 8; i++) {
                    int d = lane + 32 * i;
                    float v = Zs[d][px];
                    rowH[d] = __float2half_rn(v);
                    rowE[d] = v;
                }
            }
        }
        // E: one warp per code, strided
        for (int code = c * 32 + wid; code < N_CODES; code += NCTA * 32) {
            const float* src = emb + (size_t)code * DIM + lane * 8;
            __half* row = g_Eh + (size_t)code * DIM;
            float en = 0.f;
#pragma unroll
            for (int t = 0; t < 8; t++) {
                float v = src[t];
                en += v * v;
                row[lane * 8 + t] = __float2half_rn(v);
            }
#pragma unroll
            for (int o = 16; o > 0; o >>= 1)
                en += __shfl_xor_sync(0xffffffffu, en, o);
            if (lane == 0) g_norm2[code] = en;
        }
    }
    grid_bar();

    // ================= phase 2: GEMM (R12 body) =================
    {
        __half* As = (__half*)dsm;
        char* Bs = dsm + A_BYTES;
        float* Ns = (float*)(dsm + NS_OFF);

        const int mw = wid >> 3;          // 0..3
        const int nw = wid & 7;           // 0..7
        const int g = lane >> 2;
        const int tig = lane & 3;

        const int t0 = (c * NTILES_G) / NCTA;
        const int t1 = ((c + 1) * NTILES_G) / NCTA;

        const int a_row_l = (lane & 7) + ((lane >> 3) & 1) * 8;
        const int a_col_l = (lane >> 4) * 8;
        const int b_row_l = ((lane >> 4) & 1) * 8 + (lane & 7);
        const int b_col_l = ((lane >> 3) & 1) * 8;

        int seg = 0;
        int t = t0;
        while (t < t1) {
            const int mt = t >> 6;
            const int tend = min(t1, (mt + 1) << 6);
            const int nchunks = (tend - t) * 4;
            const int p0 = mt * PX_CTA;

            {
                int r = tid >> 3, q = tid & 7;
                const __half* src = g_Zh + (size_t)(p0 + r) * DIM + q * 32;
                uint32_t dst = s2u(As + r * ASTR + q * 32);
#pragma unroll
                for (int j = 0; j < 4; j++) cpasync16(dst + j * 16, src + j * 8);
            }
            load_b_chunk(s2u(Bs), t, 0, tid);
            if (tid < 64)
                cpasync16(s2u(Ns + (t & 1) * NTILE + tid * 4),
                          g_norm2 + (size_t)(t & 63) * NTILE + tid * 4);
            asm volatile("cp.async.commit_group;" ::: "memory");
            load_b_chunk(s2u(Bs + BSTAGE_BYTES), t, 1, tid);
            asm volatile("cp.async.commit_group;" ::: "memory");
            load_b_chunk(s2u(Bs + 2 * BSTAGE_BYTES), t, 2, tid);
            asm volatile("cp.async.commit_group;" ::: "memory");

            float acc[2][4][4];
#pragma unroll
            for (int mq = 0; mq < 2; mq++)
#pragma unroll
                for (int nt = 0; nt < 4; nt++)
#pragma unroll
                    for (int r = 0; r < 4; r++) acc[mq][nt][r] = 0.f;

            int v1[4], v2[4];
#pragma unroll
            for (int s = 0; s < 4; s++) { v1[s] = INT_MIN; v2[s] = INT_MIN; }

            for (int cc = 0; cc < nchunks; cc++) {
                asm volatile("cp.async.wait_group 2;" ::: "memory");
                __syncthreads();

                if (cc + 3 < nchunks) {
                    const int nx = cc + 3;
                    const int tt = t + (nx >> 2), kn = nx & 3;
                    load_b_chunk(s2u(Bs + (nx & 3) * BSTAGE_BYTES), tt, kn, tid);
                    if (kn == 0 && tid < 64)
                        cpasync16(s2u(Ns + (tt & 1) * NTILE + tid * 4),
                                  g_norm2 + (size_t)(tt & 63) * NTILE + tid * 4);
                }
                asm volatile("cp.async.commit_group;" ::: "memory");

                const char* sb = Bs + (cc & 3) * BSTAGE_BYTES;
                const int kb0 = (cc & 3) * KC;
#pragma unroll
                for (int s = 0; s < 4; s++) {
                    uint32_t a[2][4];
#pragma unroll
                    for (int mq = 0; mq < 2; mq++) {
                        uint32_t addr = s2u(As + (mw * 32 + mq * 16 + a_row_l) *
                                            ASTR + kb0 + s * 16 + a_col_l);
                        ldsm4(a[mq], addr);
                    }
                    uint32_t b[4][2];
#pragma unroll
                    for (int np = 0; np < 2; np++) {
                        uint32_t r[4];
                        uint32_t addr = s2u(sb + (nw * 32 + np * 16 + b_row_l) *
                                            (BSTR * 2) + (s * 16 + b_col_l) * 2);
                        ldsm4(r, addr);
                        b[2 * np][0] = r[0]; b[2 * np][1] = r[1];
                        b[2 * np + 1][0] = r[2]; b[2 * np + 1][1] = r[3];
                    }
#pragma unroll
                    for (int mq = 0; mq < 2; mq++)
#pragma unroll
                        for (int nt = 0; nt < 4; nt++)
                            mma_f16(acc[mq][nt], a[mq], b[nt]);
                }

                if ((cc & 3) == 3) {
                    const int ti = t + (cc >> 2);
                    const float2* nsp = (const float2*)(Ns + (ti & 1) * NTILE);
                    const int cb = (ti & 63) * NTILE;
#pragma unroll
                    for (int nt = 0; nt < 4; nt++) {
                        float2 nn = nsp[nw * 16 + nt * 4 + tig];
                        const int c0 = cb + nw * 32 + nt * 8 + 2 * tig;
#pragma unroll
                        for (int mq = 0; mq < 2; mq++) {
#pragma unroll
                            for (int r = 0; r < 4; r++) {
                                float nrm = (r & 1) ? nn.y : nn.x;
                                float sv = fmaf(nrm, -0.5f, acc[mq][nt][r]);
                                int key = __float2int_rn(sv * 128.0f) * 16384 +
                                          (c0 + (r & 1));
                                const int sl = mq * 2 + (r >> 1);
                                int nv1 = max(v1[sl], key);
                                v2[sl] = max(v2[sl], min(v1[sl], key));
                                v1[sl] = nv1;
                                acc[mq][nt][r] = 0.f;
                            }
                        }
                    }
                }
            }

            // segment epilogue: drain, block-reduce top-2, flush
            asm volatile("cp.async.wait_group 0;" ::: "memory");
            __syncthreads();
            int2* red = (int2*)dsm;   // [128 px][32 contributors]
#pragma unroll
            for (int s = 0; s < 4; s++) {
                int pxl = mw * 32 + (s >> 1) * 16 + (s & 1) * 8 + g;
                red[pxl * 32 + nw * 4 + tig] = make_int2(v1[s], v2[s]);
            }
            __syncthreads();
            if (tid < PX_CTA) {
                int bv1 = INT_MIN, bv2 = INT_MIN;
#pragma unroll
                for (int q = 0; q < 32; q++) {
                    int2 e = red[tid * 32 + q];
                    int nv1 = max(bv1, e.x);
                    bv2 = max(bv2, min(bv1, e.x));
                    bv1 = nv1;
                    nv1 = max(bv1, e.y);
                    bv2 = max(bv2, min(bv1, e.y));
                    bv1 = nv1;
                }
                g_seg[(c * 2 + seg) * PX_CTA + tid] = make_int2(bv1, bv2);
            }
            if (tid == 0) g_segmt[c * 2 + seg] = mt;
            __syncthreads();

            seg++;
            t = tend;
        }
        if (seg < 2 && tid == 0) g_segmt[c * 2 + 1] = -1;
    }
    grid_bar();

    // ================= phase 3: merge + rescore + gather (CTAs 0..127) ====
    if (c < N_PIX / PX_CTA) {
        int* s_mt = (int*)dsm;                       // 296 ints
        int2* s_cand = (int2*)(dsm + 2048);          // 128 int2
        int* s_sel = (int*)(dsm + 4096);             // 128 int
        const int mt = c;
        const int p0 = mt * PX_CTA;

        for (int j = tid; j < NCTA * 2; j += GT) s_mt[j] = g_segmt[j];
        __syncthreads();

        if (tid < PX_CTA) {
            int bv1 = INT_MIN, bv2 = INT_MIN;
            for (int j = 0; j < NCTA * 2; j++) {
                if (s_mt[j] == mt) {
                    int2 e = g_seg[j * PX_CTA + tid];
                    int nv1 = max(bv1, e.x);
                    bv2 = max(bv2, min(bv1, e.x));
                    bv1 = nv1;
                    nv1 = max(bv1, e.y);
                    bv2 = max(bv2, min(bv1, e.y));
                    bv1 = nv1;
                }
            }
            s_cand[tid] = make_int2(bv1 & 16383, bv2 & 16383);
        }
        __syncthreads();

        // exact fp32 rescore: 32 warps x 4 pixels
#pragma unroll 1
        for (int j = 0; j < 4; j++) {
            const int pxl = wid * 4 + j;
            const int px = p0 + pxl;
            const int2 cand = s_cand[pxl];
            const float4* zp = (const float4*)(g_Zte + (size_t)px * DIM);
            const float4* e1 = (const float4*)(emb + (size_t)cand.x * DIM);
            const float4* e2 = (const float4*)(emb + (size_t)cand.y * DIM);
            float d1 = 0.f, d2 = 0.f;
#pragma unroll
            for (int q = 0; q < 2; q++) {
                float4 zv = zp[lane + 32 * q];
                float4 a = e1[lane + 32 * q];
                float4 b = e2[lane + 32 * q];
                d1 += zv.x * a.x + zv.y * a.y + zv.z * a.z + zv.w * a.w;
                d2 += zv.x * b.x + zv.y * b.y + zv.z * b.z + zv.w * b.w;
            }
#pragma unroll
            for (int o = 16; o > 0; o >>= 1) {
                d1 += __shfl_xor_sync(0xffffffffu, d1, o);
                d2 += __shfl_xor_sync(0xffffffffu, d2, o);
            }
            if (lane == 0) {
                float s1 = d1 - 0.5f * g_norm2[cand.x];
                float s2 = d2 - 0.5f * g_norm2[cand.y];
                int best;
                if (s1 > s2) best = cand.x;
                else if (s2 > s1) best = cand.y;
                else best = min(cand.x, cand.y);
                s_sel[pxl] = best;
                out[IDX_OFF + px] = (float)best;
            }
        }
        __syncthreads();

        // gather z_q in NCHW
        const int b = p0 >> 10;
        const int hw0 = p0 & (HW - 1);
        for (int i = tid; i < DIM * PX_CTA; i += GT) {
            int d = i >> 7, pxl = i & 127;
            out[((size_t)b * DIM + d) * HW + hw0 + pxl] =
                emb[(size_t)s_sel[pxl] * DIM + d];
        }
        if (c == 0 && tid == 0) out[LOSS_OFF] = 0.f;
    }
}

// ---------------------------------------------------------------------------
extern "C" void kernel_launch(void* const* d_in, const int* in_sizes, int n_in,
                              void* d_out, int out_size) {
    const float* z = (const float*)d_in[0];
    const float* emb = (const float*)d_in[1];
    float* out = (float*)d_out;
    (void)in_sizes; (void)n_in; (void)out_size;

    static bool attr_set = false;
    if (!attr_set) {
        cudaFuncSetAttribute(vq_fused_kernel,
                             cudaFuncAttributeMaxDynamicSharedMemorySize,
                             DYN_BYTES);
        attr_set = true;
    }

    vq_fused_kernel<<<NCTA, GT, DYN_BYTES>>>(z, emb, out);
}

// round 16
// speedup vs baseline: 1.2500x; 1.0190x over previous
#include <cuda_runtime.h>
#include <cuda_fp16.h>
#include <cstdint>

#define N_PIX   16384
#define N_CODES 16384
#define DIM     256
#define HW      1024

#define PX_CTA  128
#define NTILE   256
#define KC      64
#define NCTA    148
#define NTILES_G 8192               // 128 px-tiles x 64 code-tiles
#define GT      1024                // 32 warps: 4M x 8N, warp tile 32x32

#define ASTR    264                 // A smem row stride (f16)
#define BSTR    72                  // B smem row stride (f16)
#define A_BYTES      (PX_CTA * ASTR * 2)   // 67584
#define BSTAGE_BYTES (NTILE * BSTR * 2)    // 36864
#define NSTAGE  4
#define NS_OFF  (A_BYTES + NSTAGE * BSTAGE_BYTES)
#define DYN_BYTES (NS_OFF + 2 * NTILE * 4) // 217088

#define ZQ_ELEMS (16 * DIM * HW)
#define LOSS_OFF ZQ_ELEMS
#define IDX_OFF  (ZQ_ELEMS + 1)

__device__ __half g_Zh[(size_t)N_PIX * DIM];
__device__ __half g_Eh[(size_t)N_CODES * DIM];
__device__ float  g_Zte[(size_t)N_PIX * DIM];
__device__ float  g_norm2[N_CODES];
__device__ int2   g_seg[NCTA * 2 * PX_CTA];
__device__ int    g_segmt[NCTA * 2];

// self-resetting grid barrier (wrap + phase flip; graph-replay safe)
__device__ volatile int g_phase;
__device__ unsigned int g_barcnt;

__device__ __forceinline__ void grid_bar() {
    __syncthreads();
    if (threadIdx.x == 0) {
        __threadfence();
        int ph = g_phase;
        if (atomicInc(&g_barcnt, NCTA - 1) == NCTA - 1) {
            g_phase = ph ^ 1;
        } else {
            while (g_phase == ph) { }
        }
        __threadfence();
    }
    __syncthreads();
}

__device__ __forceinline__ uint32_t s2u(const void* p) {
    return (uint32_t)__cvta_generic_to_shared(p);
}
__device__ __forceinline__ void cpasync16(uint32_t dst, const void* src) {
    asm volatile("cp.async.cg.shared.global [%0], [%1], 16;" :: "r"(dst), "l"(src));
}
__device__ __forceinline__ void ldsm4(uint32_t* r, uint32_t addr) {
    asm volatile("ldmatrix.sync.aligned.m8n8.x4.shared.b16 {%0,%1,%2,%3}, [%4];"
                 : "=r"(r[0]), "=r"(r[1]), "=r"(r[2]), "=r"(r[3]) : "r"(addr));
}
__device__ __forceinline__ void mma_f16(float* c, const uint32_t* a,
                                        const uint32_t* b) {
    asm volatile(
        "mma.sync.aligned.m16n8k16.row.col.f32.f16.f16.f32 "
        "{%0,%1,%2,%3},{%4,%5,%6,%7},{%8,%9},{%0,%1,%2,%3};"
        : "+f"(c[0]), "+f"(c[1]), "+f"(c[2]), "+f"(c[3])
        : "r"(a[0]), "r"(a[1]), "r"(a[2]), "r"(a[3]), "r"(b[0]), "r"(b[1]));
}

// ---------------------------------------------------------------------------
// Merged prep: blocks [0,512) transpose+convert z; blocks [512,2560) do E.
// ---------------------------------------------------------------------------
__global__ void __launch_bounds__(256)
prep_kernel(const float* __restrict__ z, const float* __restrict__ emb) {
    const int tid = threadIdx.x, lane = tid & 31, wid = tid >> 5;
    if (blockIdx.x < 512) {
        __shared__ float Zs[DIM][33];
        int px0 = blockIdx.x * 32;
        int b = px0 >> 10, hw0 = px0 & (HW - 1);
        for (int i = tid; i < DIM * 32; i += 256) {
            int d = i >> 5, px = i & 31;
            Zs[d][px] = z[((size_t)b * DIM + d) * HW + hw0 + px];
        }
        __syncthreads();
#pragma unroll
        for (int pp = 0; pp < 4; pp++) {
            int px = wid + pp * 8;
            __half* rowH = g_Zh + (size_t)(px0 + px) * DIM;
            float* rowE = g_Zte + (size_t)(px0 + px) * DIM;
#pragma unroll
            for (int i = 0; i < 8; i++) {
                int d = lane + 32 * i;
                float v = Zs[d][px];
                rowH[d] = __float2half_rn(v);
                rowE[d] = v;
            }
        }
    } else {
        int code = (blockIdx.x - 512) * 8 + wid;
        const float* src = emb + (size_t)code * DIM + lane * 8;
        __half* row = g_Eh + (size_t)code * DIM;
        float en = 0.f;
#pragma unroll
        for (int t = 0; t < 8; t++) {
            float v = src[t];
            en += v * v;
            row[lane * 8 + t] = __float2half_rn(v);
        }
#pragma unroll
        for (int o = 16; o > 0; o >>= 1) en += __shfl_xor_sync(0xffffffffu, en, o);
        if (lane == 0) g_norm2[code] = en;
    }
}

// ---------------------------------------------------------------------------
// B chunk loader (1024 threads): 256 rows x 64 f16 (128B); 4 threads/row.
// ---------------------------------------------------------------------------
__device__ __forceinline__ void load_b_chunk(uint32_t dstb, int tg, int kn,
                                             int tid) {
    const int row = tid >> 2, qr = tid & 3;
    const __half* src = g_Eh +
        (size_t)((tg & 63) * NTILE + row) * DIM + kn * KC + qr * 16;
    uint32_t dst = dstb + row * (BSTR * 2) + qr * 32;
    cpasync16(dst, src);
    cpasync16(dst + 16, src + 8);
}

// ---------------------------------------------------------------------------
// Fused GEMM -> grid_bar -> merge+rescore+gather. 148 persistent CTAs.
// ---------------------------------------------------------------------------
__global__ void __launch_bounds__(GT, 1)
vq_gemm_merge_kernel(const float* __restrict__ emb, float* __restrict__ out) {
    extern __shared__ char dsm[];
    const int tid = threadIdx.x;
    const int lane = tid & 31;
    const int wid = tid >> 5;
    const int c = blockIdx.x;

    // ================= phase 1: GEMM (R12 body) =================
    {
        __half* As = (__half*)dsm;
        char* Bs = dsm + A_BYTES;
        float* Ns = (float*)(dsm + NS_OFF);

        const int mw = wid >> 3;          // 0..3
        const int nw = wid & 7;           // 0..7
        const int g = lane >> 2;
        const int tig = lane & 3;

        const int t0 = (c * NTILES_G) / NCTA;
        const int t1 = ((c + 1) * NTILES_G) / NCTA;

        const int a_row_l = (lane & 7) + ((lane >> 3) & 1) * 8;
        const int a_col_l = (lane >> 4) * 8;
        const int b_row_l = ((lane >> 4) & 1) * 8 + (lane & 7);
        const int b_col_l = ((lane >> 3) & 1) * 8;

        int seg = 0;
        int t = t0;
        while (t < t1) {
            const int mt = t >> 6;
            const int tend = min(t1, (mt + 1) << 6);
            const int nchunks = (tend - t) * 4;
            const int p0 = mt * PX_CTA;

            {
                int r = tid >> 3, q = tid & 7;
                const __half* src = g_Zh + (size_t)(p0 + r) * DIM + q * 32;
                uint32_t dst = s2u(As + r * ASTR + q * 32);
#pragma unroll
                for (int j = 0; j < 4; j++) cpasync16(dst + j * 16, src + j * 8);
            }
            load_b_chunk(s2u(Bs), t, 0, tid);
            if (tid < 64)
                cpasync16(s2u(Ns + (t & 1) * NTILE + tid * 4),
                          g_norm2 + (size_t)(t & 63) * NTILE + tid * 4);
            asm volatile("cp.async.commit_group;" ::: "memory");
            load_b_chunk(s2u(Bs + BSTAGE_BYTES), t, 1, tid);
            asm volatile("cp.async.commit_group;" ::: "memory");
            load_b_chunk(s2u(Bs + 2 * BSTAGE_BYTES), t, 2, tid);
            asm volatile("cp.async.commit_group;" ::: "memory");

            float acc[2][4][4];
#pragma unroll
            for (int mq = 0; mq < 2; mq++)
#pragma unroll
                for (int nt = 0; nt < 4; nt++)
#pragma unroll
                    for (int r = 0; r < 4; r++) acc[mq][nt][r] = 0.f;

            int v1[4], v2[4];
#pragma unroll
            for (int s = 0; s < 4; s++) { v1[s] = INT_MIN; v2[s] = INT_MIN; }

            for (int cc = 0; cc < nchunks; cc++) {
                asm volatile("cp.async.wait_group 2;" ::: "memory");
                __syncthreads();

                if (cc + 3 < nchunks) {
                    const int nx = cc + 3;
                    const int tt = t + (nx >> 2), kn = nx & 3;
                    load_b_chunk(s2u(Bs + (nx & 3) * BSTAGE_BYTES), tt, kn, tid);
                    if (kn == 0 && tid < 64)
                        cpasync16(s2u(Ns + (tt & 1) * NTILE + tid * 4),
                                  g_norm2 + (size_t)(tt & 63) * NTILE + tid * 4);
                }
                asm volatile("cp.async.commit_group;" ::: "memory");

                const char* sb = Bs + (cc & 3) * BSTAGE_BYTES;
                const int kb0 = (cc & 3) * KC;
#pragma unroll
                for (int s = 0; s < 4; s++) {
                    uint32_t a[2][4];
#pragma unroll
                    for (int mq = 0; mq < 2; mq++) {
                        uint32_t addr = s2u(As + (mw * 32 + mq * 16 + a_row_l) *
                                            ASTR + kb0 + s * 16 + a_col_l);
                        ldsm4(a[mq], addr);
                    }
                    uint32_t b[4][2];
#pragma unroll
                    for (int np = 0; np < 2; np++) {
                        uint32_t r[4];
                        uint32_t addr = s2u(sb + (nw * 32 + np * 16 + b_row_l) *
                                            (BSTR * 2) + (s * 16 + b_col_l) * 2);
                        ldsm4(r, addr);
                        b[2 * np][0] = r[0]; b[2 * np][1] = r[1];
                        b[2 * np + 1][0] = r[2]; b[2 * np + 1][1] = r[3];
                    }
#pragma unroll
                    for (int mq = 0; mq < 2; mq++)
#pragma unroll
                        for (int nt = 0; nt < 4; nt++)
                            mma_f16(acc[mq][nt], a[mq], b[nt]);
                }

                if ((cc & 3) == 3) {
                    const int ti = t + (cc >> 2);
                    const float2* nsp = (const float2*)(Ns + (ti & 1) * NTILE);
                    const int cb = (ti & 63) * NTILE;
#pragma unroll
                    for (int nt = 0; nt < 4; nt++) {
                        float2 nn = nsp[nw * 16 + nt * 4 + tig];
                        const int c0 = cb + nw * 32 + nt * 8 + 2 * tig;
#pragma unroll
                        for (int mq = 0; mq < 2; mq++) {
#pragma unroll
                            for (int r = 0; r < 4; r++) {
                                float nrm = (r & 1) ? nn.y : nn.x;
                                float sv = fmaf(nrm, -0.5f, acc[mq][nt][r]);
                                int key = __float2int_rn(sv * 128.0f) * 16384 +
                                          (c0 + (r & 1));
                                const int sl = mq * 2 + (r >> 1);
                                int nv1 = max(v1[sl], key);
                                v2[sl] = max(v2[sl], min(v1[sl], key));
                                v1[sl] = nv1;
                                acc[mq][nt][r] = 0.f;
                            }
                        }
                    }
                }
            }

            // segment epilogue: drain, block-reduce top-2, flush
            asm volatile("cp.async.wait_group 0;" ::: "memory");
            __syncthreads();
            int2* red = (int2*)dsm;   // [128 px][32 contributors]
#pragma unroll
            for (int s = 0; s < 4; s++) {
                int pxl = mw * 32 + (s >> 1) * 16 + (s & 1) * 8 + g;
                red[pxl * 32 + nw * 4 + tig] = make_int2(v1[s], v2[s]);
            }
            __syncthreads();
            if (tid < PX_CTA) {
                int bv1 = INT_MIN, bv2 = INT_MIN;
#pragma unroll
                for (int q = 0; q < 32; q++) {
                    int2 e = red[tid * 32 + q];
                    int nv1 = max(bv1, e.x);
                    bv2 = max(bv2, min(bv1, e.x));
                    bv1 = nv1;
                    nv1 = max(bv1, e.y);
                    bv2 = max(bv2, min(bv1, e.y));
                    bv1 = nv1;
                }
                g_seg[(c * 2 + seg) * PX_CTA + tid] = make_int2(bv1, bv2);
            }
            if (tid == 0) g_segmt[c * 2 + seg] = mt;
            __syncthreads();

            seg++;
            t = tend;
        }
        if (seg < 2 && tid == 0) g_segmt[c * 2 + 1] = -1;
    }
    grid_bar();

    // ================= phase 2: merge + rescore + gather (CTAs 0..127) ====
    if (c < N_PIX / PX_CTA) {
        int* s_mt = (int*)dsm;                       // 296 ints
        int2* s_cand = (int2*)(dsm + 2048);          // 128 int2
        int* s_sel = (int*)(dsm + 4096);             // 128 int
        const int mt = c;
        const int p0 = mt * PX_CTA;

        for (int j = tid; j < NCTA * 2; j += GT) s_mt[j] = g_segmt[j];
        __syncthreads();

        if (tid < PX_CTA) {
            int bv1 = INT_MIN, bv2 = INT_MIN;
            for (int j = 0; j < NCTA * 2; j++) {
                if (s_mt[j] == mt) {
                    int2 e = g_seg[j * PX_CTA + tid];
                    int nv1 = max(bv1, e.x);
                    bv2 = max(bv2, min(bv1, e.x));
                    bv1 = nv1;
                    nv1 = max(bv1, e.y);
                    bv2 = max(bv2, min(bv1, e.y));
                    bv1 = nv1;
                }
            }
            s_cand[tid] = make_int2(bv1 & 16383, bv2 & 16383);
        }
        __syncthreads();

        // exact fp32 rescore: 32 warps x 4 pixels
#pragma unroll 1
        for (int j = 0; j < 4; j++) {
            const int pxl = wid * 4 + j;
            const int px = p0 + pxl;
            const int2 cand = s_cand[pxl];
            const float4* zp = (const float4*)(g_Zte + (size_t)px * DIM);
            const float4* e1 = (const float4*)(emb + (size_t)cand.x * DIM);
            const float4* e2 = (const float4*)(emb + (size_t)cand.y * DIM);
            float d1 = 0.f, d2 = 0.f;
#pragma unroll
            for (int q = 0; q < 2; q++) {
                float4 zv = zp[lane + 32 * q];
                float4 a = e1[lane + 32 * q];
                float4 b = e2[lane + 32 * q];
                d1 += zv.x * a.x + zv.y * a.y + zv.z * a.z + zv.w * a.w;
                d2 += zv.x * b.x + zv.y * b.y + zv.z * b.z + zv.w * b.w;
            }
#pragma unroll
            for (int o = 16; o > 0; o >>= 1) {
                d1 += __shfl_xor_sync(0xffffffffu, d1, o);
                d2 += __shfl_xor_sync(0xffffffffu, d2, o);
            }
            if (lane == 0) {
                float s1 = d1 - 0.5f * g_norm2[cand.x];
                float s2 = d2 - 0.5f * g_norm2[cand.y];
                int best;
                if (s1 > s2) best = cand.x;
                else if (s2 > s1) best = cand.y;
                else best = min(cand.x, cand.y);
                s_sel[pxl] = best;
                out[IDX_OFF + px] = (float)best;
            }
        }
        __syncthreads();

        // gather z_q in NCHW
        const int b = p0 >> 10;
        const int hw0 = p0 & (HW - 1);
        for (int i = tid; i < DIM * PX_CTA; i += GT) {
            int d = i >> 7, pxl = i & 127;
            out[((size_t)b * DIM + d) * HW + hw0 + pxl] =
                emb[(size_t)s_sel[pxl] * DIM + d];
        }
        if (c == 0 && tid == 0) out[LOSS_OFF] = 0.f;
    }
}

// ---------------------------------------------------------------------------
extern "C" void kernel_launch(void* const* d_in, const int* in_sizes, int n_in,
                              void* d_out, int out_size) {
    const float* z = (const float*)d_in[0];
    const float* emb = (const float*)d_in[1];
    float* out = (float*)d_out;
    (void)in_sizes; (void)n_in; (void)out_size;

    static bool attr_set = false;
    if (!attr_set) {
        cudaFuncSetAttribute(vq_gemm_merge_kernel,
                             cudaFuncAttributeMaxDynamicSharedMemorySize,
                             DYN_BYTES);
        attr_set = true;
    }

    prep_kernel<<<2560, 256>>>(z, emb);
    vq_gemm_merge_kernel<<<NCTA, GT, DYN_BYTES>>>(emb, out);
}

// round 17
// speedup vs baseline: 1.2564x; 1.0051x over previous
#include <cuda_runtime.h>
#include <cuda_fp16.h>
#include <cstdint>

#define N_PIX   16384
#define N_CODES 16384
#define DIM     256
#define HW      1024

#define PX_CTA  128
#define NTILE   128
#define KC      32
#define NCTA    296                 // 148 SMs x occupancy 2
#define NTILES_G 16384              // 128 px-tiles x 128 code-tiles
#define GT      512                 // 16 warps: 4M x 4N, warp tile 32x32

#define ASTR    264                 // A smem row stride (f16)
#define BSTR    40                  // B smem row stride (f16): 80B
#define A_BYTES      (PX_CTA * ASTR * 2)   // 67584
#define BSTAGE_BYTES (NTILE * BSTR * 2)    // 10240
#define NSTAGE  4
#define NS_OFF  (A_BYTES + NSTAGE * BSTAGE_BYTES)   // 108544
#define DYN_BYTES (NS_OFF + 2 * NTILE * 4)          // 109568

#define ZQ_ELEMS (16 * DIM * HW)
#define LOSS_OFF ZQ_ELEMS
#define IDX_OFF  (ZQ_ELEMS + 1)

__device__ __half g_Zh[(size_t)N_PIX * DIM];
__device__ __half g_Eh[(size_t)N_CODES * DIM];
__device__ float  g_Zte[(size_t)N_PIX * DIM];
__device__ float  g_norm2[N_CODES];
__device__ int2   g_seg[NCTA * 2 * PX_CTA];
__device__ int    g_segmt[NCTA * 2];

// self-resetting grid barrier (wrap + phase flip; graph-replay safe)
__device__ volatile int g_phase;
__device__ unsigned int g_barcnt;

__device__ __forceinline__ void grid_bar() {
    __syncthreads();
    if (threadIdx.x == 0) {
        __threadfence();
        int ph = g_phase;
        if (atomicInc(&g_barcnt, NCTA - 1) == NCTA - 1) {
            g_phase = ph ^ 1;
        } else {
            while (g_phase == ph) { }
        }
        __threadfence();
    }
    __syncthreads();
}

__device__ __forceinline__ uint32_t s2u(const void* p) {
    return (uint32_t)__cvta_generic_to_shared(p);
}
__device__ __forceinline__ void cpasync16(uint32_t dst, const void* src) {
    asm volatile("cp.async.cg.shared.global [%0], [%1], 16;" :: "r"(dst), "l"(src));
}
__device__ __forceinline__ void ldsm4(uint32_t* r, uint32_t addr) {
    asm volatile("ldmatrix.sync.aligned.m8n8.x4.shared.b16 {%0,%1,%2,%3}, [%4];"
                 : "=r"(r[0]), "=r"(r[1]), "=r"(r[2]), "=r"(r[3]) : "r"(addr));
}
__device__ __forceinline__ void mma_f16(float* c, const uint32_t* a,
                                        const uint32_t* b) {
    asm volatile(
        "mma.sync.aligned.m16n8k16.row.col.f32.f16.f16.f32 "
        "{%0,%1,%2,%3},{%4,%5,%6,%7},{%8,%9},{%0,%1,%2,%3};"
        : "+f"(c[0]), "+f"(c[1]), "+f"(c[2]), "+f"(c[3])
        : "r"(a[0]), "r"(a[1]), "r"(a[2]), "r"(a[3]), "r"(b[0]), "r"(b[1]));
}

// ---------------------------------------------------------------------------
// Merged prep: blocks [0,512) transpose+convert z; blocks [512,2560) do E.
// ---------------------------------------------------------------------------
__global__ void __launch_bounds__(256)
prep_kernel(const float* __restrict__ z, const float* __restrict__ emb) {
    const int tid = threadIdx.x, lane = tid & 31, wid = tid >> 5;
    if (blockIdx.x < 512) {
        __shared__ float Zs[DIM][33];
        int px0 = blockIdx.x * 32;
        int b = px0 >> 10, hw0 = px0 & (HW - 1);
        for (int i = tid; i < DIM * 32; i += 256) {
            int d = i >> 5, px = i & 31;
            Zs[d][px] = z[((size_t)b * DIM + d) * HW + hw0 + px];
        }
        __syncthreads();
#pragma unroll
        for (int pp = 0; pp < 4; pp++) {
            int px = wid + pp * 8;
            __half* rowH = g_Zh + (size_t)(px0 + px) * DIM;
            float* rowE = g_Zte + (size_t)(px0 + px) * DIM;
#pragma unroll
            for (int i = 0; i < 8; i++) {
                int d = lane + 32 * i;
                float v = Zs[d][px];
                rowH[d] = __float2half_rn(v);
                rowE[d] = v;
            }
        }
    } else {
        int code = (blockIdx.x - 512) * 8 + wid;
        const float* src = emb + (size_t)code * DIM + lane * 8;
        __half* row = g_Eh + (size_t)code * DIM;
        float en = 0.f;
#pragma unroll
        for (int t = 0; t < 8; t++) {
            float v = src[t];
            en += v * v;
            row[lane * 8 + t] = __float2half_rn(v);
        }
#pragma unroll
        for (int o = 16; o > 0; o >>= 1) en += __shfl_xor_sync(0xffffffffu, en, o);
        if (lane == 0) g_norm2[code] = en;
    }
}

// ---------------------------------------------------------------------------
// B chunk loader (512 threads): 128 rows x 32 f16 (64B); 4 threads/row.
// ---------------------------------------------------------------------------
__device__ __forceinline__ void load_b_chunk(uint32_t dstb, int tg, int kn,
                                             int tid) {
    const int row = tid >> 2, qr = tid & 3;
    const __half* src = g_Eh +
        (size_t)((tg & 127) * NTILE + row) * DIM + kn * KC + qr * 8;
    cpasync16(dstb + row * (BSTR * 2) + qr * 16, src);
}

// ---------------------------------------------------------------------------
// Fused GEMM -> grid_bar -> merge. 296 persistent CTAs (occ 2 per SM).
// ---------------------------------------------------------------------------
__global__ void __launch_bounds__(GT, 2)
vq_gemm_merge_kernel(const float* __restrict__ emb, float* __restrict__ out) {
    extern __shared__ char dsm[];
    const int tid = threadIdx.x;
    const int lane = tid & 31;
    const int wid = tid >> 5;
    const int c = blockIdx.x;

    // ================= phase 1: GEMM =================
    {
        __half* As = (__half*)dsm;
        char* Bs = dsm + A_BYTES;
        float* Ns = (float*)(dsm + NS_OFF);

        const int mw = wid >> 2;          // 0..3
        const int nw = wid & 3;           // 0..3
        const int g = lane >> 2;
        const int tig = lane & 3;

        const int t0 = (int)(((long long)c * NTILES_G) / NCTA);
        const int t1 = (int)(((long long)(c + 1) * NTILES_G) / NCTA);

        const int a_row_l = (lane & 7) + ((lane >> 3) & 1) * 8;
        const int a_col_l = (lane >> 4) * 8;
        const int b_row_l = ((lane >> 4) & 1) * 8 + (lane & 7);
        const int b_col_l = ((lane >> 3) & 1) * 8;

        int seg = 0;
        int t = t0;
        while (t < t1) {
            const int mt = t >> 7;                  // px-tile (128 code-tiles)
            const int tend = min(t1, (mt + 1) << 7);
            const int nchunks = (tend - t) * 8;     // 8 chunks per code tile
            const int p0 = mt * PX_CTA;

            // ---- segment prologue: A panel + chunks 0..2 ----
            {
                int r = tid >> 2, q = tid & 3;  // 128 rows, 4 thr/row, 128B
                const __half* src = g_Zh + (size_t)(p0 + r) * DIM + q * 64;
                uint32_t dst = s2u(As + r * ASTR + q * 64);
#pragma unroll
                for (int j = 0; j < 8; j++) cpasync16(dst + j * 16, src + j * 8);
            }
            load_b_chunk(s2u(Bs), t, 0, tid);
            if (tid < 32)
                cpasync16(s2u(Ns + (t & 1) * NTILE + tid * 4),
                          g_norm2 + (size_t)(t & 127) * NTILE + tid * 4);
            asm volatile("cp.async.commit_group;" ::: "memory");
            load_b_chunk(s2u(Bs + BSTAGE_BYTES), t, 1, tid);
            asm volatile("cp.async.commit_group;" ::: "memory");
            load_b_chunk(s2u(Bs + 2 * BSTAGE_BYTES), t, 2, tid);
            asm volatile("cp.async.commit_group;" ::: "memory");

            float acc[2][4][4];
#pragma unroll
            for (int mq = 0; mq < 2; mq++)
#pragma unroll
                for (int nt = 0; nt < 4; nt++)
#pragma unroll
                    for (int r = 0; r < 4; r++) acc[mq][nt][r] = 0.f;

            int v1[4], v2[4];
#pragma unroll
            for (int s = 0; s < 4; s++) { v1[s] = INT_MIN; v2[s] = INT_MIN; }

            for (int cc = 0; cc < nchunks; cc++) {
                asm volatile("cp.async.wait_group 2;" ::: "memory");
                __syncthreads();

                if (cc + 3 < nchunks) {
                    const int nx = cc + 3;
                    const int tt = t + (nx >> 3), kn = nx & 7;
                    load_b_chunk(s2u(Bs + (nx & 3) * BSTAGE_BYTES), tt, kn, tid);
                    if (kn == 0 && tid < 32)
                        cpasync16(s2u(Ns + (tt & 1) * NTILE + tid * 4),
                                  g_norm2 + (size_t)(tt & 127) * NTILE + tid * 4);
                }
                asm volatile("cp.async.commit_group;" ::: "memory");

                // compute chunk cc: 2 k16-steps; A k-offset = (cc&7)*KC
                const char* sb = Bs + (cc & 3) * BSTAGE_BYTES;
                const int kb0 = (cc & 7) * KC;
#pragma unroll
                for (int s = 0; s < 2; s++) {
                    uint32_t a[2][4];
#pragma unroll
                    for (int mq = 0; mq < 2; mq++) {
                        uint32_t addr = s2u(As + (mw * 32 + mq * 16 + a_row_l) *
                                            ASTR + kb0 + s * 16 + a_col_l);
                        ldsm4(a[mq], addr);
                    }
                    uint32_t b[4][2];
#pragma unroll
                    for (int np = 0; np < 2; np++) {
                        uint32_t r[4];
                        uint32_t addr = s2u(sb + (nw * 32 + np * 16 + b_row_l) *
                                            (BSTR * 2) + (s * 16 + b_col_l) * 2);
                        ldsm4(r, addr);
                        b[2 * np][0] = r[0]; b[2 * np][1] = r[1];
                        b[2 * np + 1][0] = r[2]; b[2 * np + 1][1] = r[3];
                    }
#pragma unroll
                    for (int mq = 0; mq < 2; mq++)
#pragma unroll
                        for (int nt = 0; nt < 4; nt++)
                            mma_f16(acc[mq][nt], a[mq], b[nt]);
                }

                // fold code-tile every 8 chunks (branch-free packed top-2)
                if ((cc & 7) == 7) {
                    const int ti = t + (cc >> 3);
                    const float2* nsp = (const float2*)(Ns + (ti & 1) * NTILE);
                    const int cb = (ti & 127) * NTILE;
#pragma unroll
                    for (int nt = 0; nt < 4; nt++) {
                        float2 nn = nsp[nw * 16 + nt * 4 + tig];
                        const int c0 = cb + nw * 32 + nt * 8 + 2 * tig;
#pragma unroll
                        for (int mq = 0; mq < 2; mq++) {
#pragma unroll
                            for (int r = 0; r < 4; r++) {
                                float nrm = (r & 1) ? nn.y : nn.x;
                                float sv = fmaf(nrm, -0.5f, acc[mq][nt][r]);
                                int key = __float2int_rn(sv * 128.0f) * 16384 +
                                          (c0 + (r & 1));
                                const int sl = mq * 2 + (r >> 1);
                                int nv1 = max(v1[sl], key);
                                v2[sl] = max(v2[sl], min(v1[sl], key));
                                v1[sl] = nv1;
                                acc[mq][nt][r] = 0.f;
                            }
                        }
                    }
                }
            }

            // segment epilogue: drain, block-reduce top-2, flush
            asm volatile("cp.async.wait_group 0;" ::: "memory");
            __syncthreads();
            int2* red = (int2*)dsm;   // [128 px][16 contributors]
#pragma unroll
            for (int s = 0; s < 4; s++) {
                int pxl = mw * 32 + (s >> 1) * 16 + (s & 1) * 8 + g;
                red[pxl * 16 + nw * 4 + tig] = make_int2(v1[s], v2[s]);
            }
            __syncthreads();
            if (tid < PX_CTA) {
                int bv1 = INT_MIN, bv2 = INT_MIN;
#pragma unroll
                for (int q = 0; q < 16; q++) {
                    int2 e = red[tid * 16 + q];
                    int nv1 = max(bv1, e.x);
                    bv2 = max(bv2, min(bv1, e.x));
                    bv1 = nv1;
                    nv1 = max(bv1, e.y);
                    bv2 = max(bv2, min(bv1, e.y));
                    bv1 = nv1;
                }
                g_seg[(c * 2 + seg) * PX_CTA + tid] = make_int2(bv1, bv2);
            }
            if (tid == 0) g_segmt[c * 2 + seg] = mt;
            __syncthreads();

            seg++;
            t = tend;
        }
        if (seg < 2 && tid == 0) g_segmt[c * 2 + 1] = -1;
    }
    grid_bar();

    // ================= phase 2: merge + rescore + gather (CTAs 0..127) ====
    if (c < N_PIX / PX_CTA) {
        int* s_mt = (int*)dsm;                       // 592 ints
        int2* s_cand = (int2*)(dsm + 4096);          // 128 int2
        int* s_sel = (int*)(dsm + 8192);             // 128 int
        const int mt = c;
        const int p0 = mt * PX_CTA;

        for (int j = tid; j < NCTA * 2; j += GT) s_mt[j] = g_segmt[j];
        __syncthreads();

        if (tid < PX_CTA) {
            int bv1 = INT_MIN, bv2 = INT_MIN;
            for (int j = 0; j < NCTA * 2; j++) {
                if (s_mt[j] == mt) {
                    int2 e = g_seg[j * PX_CTA + tid];
                    int nv1 = max(bv1, e.x);
                    bv2 = max(bv2, min(bv1, e.x));
                    bv1 = nv1;
                    nv1 = max(bv1, e.y);
                    bv2 = max(bv2, min(bv1, e.y));
                    bv1 = nv1;
                }
            }
            s_cand[tid] = make_int2(bv1 & 16383, bv2 & 16383);
        }
        __syncthreads();

        // exact fp32 rescore: 16 warps x 8 pixels
#pragma unroll 1
        for (int j = 0; j < 8; j++) {
            const int pxl = wid * 8 + j;
            const int px = p0 + pxl;
            const int2 cand = s_cand[pxl];
            const float4* zp = (const float4*)(g_Zte + (size_t)px * DIM);
            const float4* e1 = (const float4*)(emb + (size_t)cand.x * DIM);
            const float4* e2 = (const float4*)(emb + (size_t)cand.y * DIM);
            float d1 = 0.f, d2 = 0.f;
#pragma unroll
            for (int q = 0; q < 2; q++) {
                float4 zv = zp[lane + 32 * q];
                float4 a = e1[lane + 32 * q];
                float4 b = e2[lane + 32 * q];
                d1 += zv.x * a.x + zv.y * a.y + zv.z * a.z + zv.w * a.w;
                d2 += zv.x * b.x + zv.y * b.y + zv.z * b.z + zv.w * b.w;
            }
#pragma unroll
            for (int o = 16; o > 0; o >>= 1) {
                d1 += __shfl_xor_sync(0xffffffffu, d1, o);
                d2 += __shfl_xor_sync(0xffffffffu, d2, o);
            }
            if (lane == 0) {
                float s1 = d1 - 0.5f * g_norm2[cand.x];
                float s2 = d2 - 0.5f * g_norm2[cand.y];
                int best;
                if (s1 > s2) best = cand.x;
                else if (s2 > s1) best = cand.y;
                else best = min(cand.x, cand.y);
                s_sel[pxl] = best;
                out[IDX_OFF + px] = (float)best;
            }
        }
        __syncthreads();

        // gather z_q in NCHW
        const int b = p0 >> 10;
        const int hw0 = p0 & (HW - 1);
        for (int i = tid; i < DIM * PX_CTA; i += GT) {
            int d = i >> 7, pxl = i & 127;
            out[((size_t)b * DIM + d) * HW + hw0 + pxl] =
                emb[(size_t)s_sel[pxl] * DIM + d];
        }
        if (c == 0 && tid == 0) out[LOSS_OFF] = 0.f;
    }
}

// ---------------------------------------------------------------------------
extern "C" void kernel_launch(void* const* d_in, const int* in_sizes, int n_in,
                              void* d_out, int out_size) {
    const float* z = (const float*)d_in[0];
    const float* emb = (const float*)d_in[1];
    float* out = (float*)d_out;
    (void)in_sizes; (void)n_in; (void)out_size;

    static bool attr_set = false;
    if (!attr_set) {
        cudaFuncSetAttribute(vq_gemm_merge_kernel,
                             cudaFuncAttributeMaxDynamicSharedMemorySize,
                             DYN_BYTES);
        attr_set = true;
    }

    prep_kernel<<<2560, 256>>>(z, emb);
    vq_gemm_merge_kernel<<<NCTA, GT, DYN_BYTES>>>(emb, out);
}